// round 2
// baseline (speedup 1.0000x reference)
#include <cuda_runtime.h>
#include <cuda_bf16.h>

// yolov8_GradCamLoss: out = sum(x0) + sum(x1) + sum(x2)
// Pure HBM-bandwidth-bound: 225.8 MB fp32 read -> 1 scalar.
// Roofline: ~28 us at 8 TB/s; target 32-38 us.

__global__ void zero_out_kernel(float* out) {
    out[0] = 0.0f;
}

__global__ __launch_bounds__(256) void sum3_kernel(
    const float4* __restrict__ a, long long na4,
    const float4* __restrict__ b, long long nb4,
    const float4* __restrict__ c, long long nc4,
    float* __restrict__ out)
{
    const long long tid    = (long long)blockIdx.x * blockDim.x + threadIdx.x;
    const long long stride = (long long)gridDim.x * blockDim.x;

    float s = 0.0f;

    // Grid-stride, largest tensor first. float4 -> LDG.E.128, coalesced,
    // ptxas front-batches independent iterations for deep MLP.
    for (long long i = tid; i < na4; i += stride) {
        float4 v = a[i];
        s += (v.x + v.y) + (v.z + v.w);
    }
    for (long long i = tid; i < nb4; i += stride) {
        float4 v = b[i];
        s += (v.x + v.y) + (v.z + v.w);
    }
    for (long long i = tid; i < nc4; i += stride) {
        float4 v = c[i];
        s += (v.x + v.y) + (v.z + v.w);
    }

    // Warp reduction
    #pragma unroll
    for (int off = 16; off > 0; off >>= 1)
        s += __shfl_xor_sync(0xFFFFFFFFu, s, off);

    // Block reduction via shared memory
    __shared__ float warp_sums[8];  // 256 threads = 8 warps
    const int lane = threadIdx.x & 31;
    const int wid  = threadIdx.x >> 5;
    if (lane == 0) warp_sums[wid] = s;
    __syncthreads();

    if (wid == 0) {
        s = (lane < 8) ? warp_sums[lane] : 0.0f;
        #pragma unroll
        for (int off = 4; off > 0; off >>= 1)
            s += __shfl_xor_sync(0xFFFFFFFFu, s, off);
        if (lane == 0)
            atomicAdd(out, s);
    }
}

extern "C" void kernel_launch(void* const* d_in, const int* in_sizes, int n_in,
                              void* d_out, int out_size)
{
    const float* x0 = (const float*)d_in[0];
    const float* x1 = (const float*)d_in[1];
    const float* x2 = (const float*)d_in[2];
    float* out = (float*)d_out;

    const long long n0 = in_sizes[0];  // 43,008,000 (512000 x 84)
    const long long n1 = in_sizes[1];  // 10,752,000 (128000 x 84)
    const long long n2 = in_sizes[2];  //  2,688,000 ( 32000 x 84)
    // All element counts divisible by 4.
    const long long n0_4 = n0 >> 2;
    const long long n1_4 = n1 >> 2;
    const long long n2_4 = n2 >> 2;

    zero_out_kernel<<<1, 1>>>(out);

    // 148 SMs x 8 CTAs: balanced single-wave-ish occupancy, deep L1tex queue.
    const int threads = 256;
    const int blocks  = 148 * 8;
    sum3_kernel<<<blocks, threads>>>(
        (const float4*)x0, n0_4,
        (const float4*)x1, n1_4,
        (const float4*)x2, n2_4,
        out);
}